// round 9
// baseline (speedup 1.0000x reference)
#include <cuda_runtime.h>
#include <math.h>

// Problem dims (fixed by reference)
#define B    128
#define N    2048
#define H    768
#define H2   1536
#define S    8            // N-splits for pooling (grid.x)
#define NPS  (N / S)      // 256 rows per split
#define NBLK (S * B)      // 1024 blocks; 148 SMs x 7 = 1036 >= 1024 -> all resident
#define KT3  16           // gemm k-splits       (48 k each)
#define FT3  32           // gemm f-tiles        (48 f each)
#define LN_EPS 1e-5f

// Scratch (static device globals; no allocation allowed)
__device__ float g_partial[B * S * H];       // 3.1 MB
__device__ float g_pooled[B * H];            // 393 KB
__device__ float g_hp[KT3 * B * H2];         // 12.6 MB gemm k-split partials

// grid-barrier state (epoch-based, separate counter per barrier slot)
__device__ unsigned g_cnt[4] = {0u, 0u, 0u, 0u};
__device__ unsigned g_bar_gen = 0u;

// All blocks arrive; only blocks with do_wait poll for release. Separate
// counters per (target & 3) let non-dependent blocks skip waiting safely.
__device__ __forceinline__ void gbar(unsigned target, bool do_wait) {
    __threadfence();
    __syncthreads();
    if (threadIdx.x == 0) {
        const unsigned idx = target & 3u;
        if (atomicAdd(&g_cnt[idx], 1u) == (unsigned)(NBLK - 1)) {
            g_cnt[idx] = 0u;
            __threadfence();
            *(volatile unsigned*)&g_bar_gen = target;
        } else if (do_wait) {
            while ((int)(*(volatile unsigned*)&g_bar_gen - target) < 0)
                __nanosleep(32);
        }
    }
    __syncthreads();
}

// ---------------------------------------------------------------------------
// ONE persistent kernel: pool -> fold -> gemm -> gelu+LN+head.
// grid = (S=8, B=128) = 1024 blocks, 192 threads, 7 blocks/SM guaranteed
// (regs<=48 via launch_bounds, 7.4KB smem -> 52KB/SM).
// ---------------------------------------------------------------------------
__global__ void __launch_bounds__(192, 7) fused_all(
    const float* __restrict__ v,  const float* __restrict__ W1,
    const float* __restrict__ b1, const float* __restrict__ gamma,
    const float* __restrict__ beta, const float* __restrict__ W2,
    const float* __restrict__ b2, float* __restrict__ out)
{
    __shared__ __align__(16) float sp[16][68];   // pooled^T k-chunk  [k][b]
    __shared__ __align__(16) float sw[16][48];   // W1 k-chunk        [k][f]
    __shared__ float redA[6], redB[6];

    const int t    = threadIdx.x;       // 0..191
    const int sblk = blockIdx.x;        // 0..7
    const int b    = blockIdx.y;        // 0..127

    // epoch base: every thread's read precedes its block's first arrival,
    // which precedes the first release -> consistent across the grid.
    const unsigned gen0 = *(volatile unsigned*)&g_bar_gen;

    // ======== Phase 1: partial mean-pool (85%-of-spec streaming) ========
    {
        const float4* p = reinterpret_cast<const float4*>(
            v + ((size_t)b * N + (size_t)sblk * NPS) * H) + t;
        const int stride = H / 4;

        float4 a0 = make_float4(0.f,0.f,0.f,0.f), a1 = a0, a2 = a0, a3 = a0;
        #pragma unroll 1
        for (int n = 0; n < NPS; n += 4) {
            float4 x0 = __ldcs(p + (n + 0) * stride);
            float4 x1 = __ldcs(p + (n + 1) * stride);
            float4 x2 = __ldcs(p + (n + 2) * stride);
            float4 x3 = __ldcs(p + (n + 3) * stride);
            a0.x += x0.x; a0.y += x0.y; a0.z += x0.z; a0.w += x0.w;
            a1.x += x1.x; a1.y += x1.y; a1.z += x1.z; a1.w += x1.w;
            a2.x += x2.x; a2.y += x2.y; a2.z += x2.z; a2.w += x2.w;
            a3.x += x3.x; a3.y += x3.y; a3.z += x3.z; a3.w += x3.w;
        }
        float4 acc;
        acc.x = (a0.x + a1.x) + (a2.x + a3.x);
        acc.y = (a0.y + a1.y) + (a2.y + a3.y);
        acc.z = (a0.z + a1.z) + (a2.z + a3.z);
        acc.w = (a0.w + a1.w) + (a2.w + a3.w);
        *(reinterpret_cast<float4*>(g_partial + ((size_t)b * S + sblk) * H) + t) = acc;
    }

    // barrier 1: only fold blocks (sblk==0) need the release
    gbar(gen0 + 1u, sblk == 0);

    // ======== Phase 2: fold S partials -> g_pooled (128 blocks) ========
    if (sblk == 0) {
        float4 r = make_float4(0.f, 0.f, 0.f, 0.f);
        #pragma unroll
        for (int ss = 0; ss < S; ss++) {
            float4 x = *(reinterpret_cast<const float4*>(
                g_partial + ((size_t)b * S + ss) * H) + t);
            r.x += x.x; r.y += x.y; r.z += x.z; r.w += x.w;
        }
        const float inv = 1.0f / (float)N;
        r.x *= inv; r.y *= inv; r.z *= inv; r.w *= inv;
        *(reinterpret_cast<float4*>(g_pooled + (size_t)b * H) + t) = r;
    }

    // barrier 2: everyone needs g_pooled
    gbar(gen0 + 2u, true);

    // ======== Phase 3: GEMM partials, all 1024 blocks (balanced) ========
    // tile decomposition: flat = bt(2) x ft(32) x kt(16); 64b x 48f x 48k each
    {
        const int flat = b * 8 + sblk;          // 0..1023
        const int kt = flat & 15;
        const int ft = (flat >> 4) & 31;
        const int bt = flat >> 9;
        const int k0 = kt * 48, f0 = ft * 48, b0 = bt * 64;
        const int tx = t % 12, ty = t / 12;     // 12 f-groups x 16 b-groups

        float acc[4][4];
        #pragma unroll
        for (int i = 0; i < 4; i++)
            #pragma unroll
            for (int j = 0; j < 4; j++) acc[i][j] = 0.f;

        #pragma unroll 1
        for (int c = 0; c < 3; c++) {
            const int kc = k0 + c * 16;
            #pragma unroll
            for (int i = t; i < 16 * 64; i += 192) {
                int kk = i & 15, bb = i >> 4;
                sp[kk][bb] = g_pooled[(b0 + bb) * H + kc + kk];
            }
            #pragma unroll
            for (int i = t; i < 16 * 48; i += 192) {
                int ff = i % 48, kk = i / 48;
                sw[kk][ff] = W1[(size_t)(kc + kk) * H2 + f0 + ff];
            }
            __syncthreads();
            #pragma unroll
            for (int kk = 0; kk < 16; kk++) {
                float4 wv = *reinterpret_cast<const float4*>(&sw[kk][tx * 4]);
                float4 pv = *reinterpret_cast<const float4*>(&sp[kk][ty * 4]);
                const float pb[4] = {pv.x, pv.y, pv.z, pv.w};
                const float wf[4] = {wv.x, wv.y, wv.z, wv.w};
                #pragma unroll
                for (int bi = 0; bi < 4; bi++)
                    #pragma unroll
                    for (int fi = 0; fi < 4; fi++)
                        acc[bi][fi] += pb[bi] * wf[fi];
            }
            __syncthreads();
        }

        float* dst = g_hp + (size_t)kt * (B * H2);
        #pragma unroll
        for (int bi = 0; bi < 4; bi++) {
            int row = b0 + ty * 4 + bi;
            float4 o = make_float4(acc[bi][0], acc[bi][1], acc[bi][2], acc[bi][3]);
            *reinterpret_cast<float4*>(dst + (size_t)row * H2 + f0 + tx * 4) = o;
        }
    }

    // barrier 3: only ln blocks (sblk==0) need the release; others exit
    gbar(gen0 + 3u, sblk == 0);
    if (sblk != 0) return;

    // ======== Phase 4: fold KT3 partials + bias + GELU + LN + head ========
    {
        const int w = t >> 5, l = t & 31;       // 6 warps
        const size_t rowoff = (size_t)b * H2;
        const float r2 = 0.70710678118654752f;

        float4 xv[2];
        float s = 0.f, sq = 0.f;
        #pragma unroll
        for (int half = 0; half < 2; half++) {
            const int pos = t + half * 192;     // float4 index 0..383
            float4 a = *reinterpret_cast<const float4*>(b1 + pos * 4);
            float h0 = a.x, h1 = a.y, h2 = a.z, h3 = a.w;
            #pragma unroll
            for (int ksp = 0; ksp < KT3; ksp++) {
                float4 pp = *reinterpret_cast<const float4*>(
                    g_hp + (size_t)ksp * (B * H2) + rowoff + pos * 4);
                h0 += pp.x; h1 += pp.y; h2 += pp.z; h3 += pp.w;
            }
            float4 x;
            x.x = 0.5f * h0 * (1.0f + erff(h0 * r2));
            x.y = 0.5f * h1 * (1.0f + erff(h1 * r2));
            x.z = 0.5f * h2 * (1.0f + erff(h2 * r2));
            x.w = 0.5f * h3 * (1.0f + erff(h3 * r2));
            xv[half] = x;
            s  += (x.x + x.y) + (x.z + x.w);
            sq += (x.x * x.x + x.y * x.y) + (x.z * x.z + x.w * x.w);
        }

        #pragma unroll
        for (int o = 16; o; o >>= 1) {
            s  += __shfl_xor_sync(0xFFFFFFFFu, s,  o);
            sq += __shfl_xor_sync(0xFFFFFFFFu, sq, o);
        }
        if (l == 0) { redA[w] = s; redB[w] = sq; }
        __syncthreads();
        if (t < 32) {
            float a  = (l < 6) ? redA[l] : 0.f;
            float bq = (l < 6) ? redB[l] : 0.f;
            #pragma unroll
            for (int o = 4; o; o >>= 1) {
                a  += __shfl_xor_sync(0xFFFFFFFFu, a,  o);
                bq += __shfl_xor_sync(0xFFFFFFFFu, bq, o);
            }
            if (l == 0) { redA[0] = a; redB[0] = bq; }
        }
        __syncthreads();

        const float mu   = redA[0] * (1.0f / (float)H2);
        const float var  = redB[0] * (1.0f / (float)H2) - mu * mu;
        const float rstd = rsqrtf(var + LN_EPS);
        __syncthreads();   // protect redA/redB reuse

        float local = 0.f;
        #pragma unroll
        for (int half = 0; half < 2; half++) {
            const int pos = t + half * 192;
            float4 gm = *reinterpret_cast<const float4*>(gamma + pos * 4);
            float4 bt = *reinterpret_cast<const float4*>(beta  + pos * 4);
            float4 w2 = *reinterpret_cast<const float4*>(W2    + pos * 4);
            float4 x = xv[half];
            float y0 = (x.x - mu) * rstd * gm.x + bt.x;
            float y1 = (x.y - mu) * rstd * gm.y + bt.y;
            float y2 = (x.z - mu) * rstd * gm.z + bt.z;
            float y3 = (x.w - mu) * rstd * gm.w + bt.w;
            local += (y0 * w2.x + y1 * w2.y) + (y2 * w2.z + y3 * w2.w);
        }
        #pragma unroll
        for (int o = 16; o; o >>= 1)
            local += __shfl_xor_sync(0xFFFFFFFFu, local, o);
        if (l == 0) redA[w] = local;
        __syncthreads();
        if (t < 32) {
            float a = (l < 6) ? redA[l] : 0.f;
            #pragma unroll
            for (int o = 4; o; o >>= 1)
                a += __shfl_xor_sync(0xFFFFFFFFu, a, o);
            if (l == 0) redA[0] = a;
        }
        __syncthreads();

        const float pred = redA[0] + b2[0];
        if (t == 0) out[b] = pred;

        // one-hot logits: round-half-even matches jnp.round; clamp [0,15]
        if (t < 16) {
            float r = rintf(pred);
            r = fminf(fmaxf(r, 0.f), 15.f);
            int aid = (int)r;
            out[B + b * 16 + t] = (t == aid) ? 1.0f : 0.0f;
        }
    }
}

// ---------------------------------------------------------------------------
extern "C" void kernel_launch(void* const* d_in, const int* in_sizes, int n_in,
                              void* d_out, int out_size) {
    const float* v_emb = (const float*)d_in[0];  // [B,N,H]
    const float* W1    = (const float*)d_in[1];  // [H,2H]
    const float* b1    = (const float*)d_in[2];  // [2H]
    const float* gamma = (const float*)d_in[3];  // [2H]
    const float* beta  = (const float*)d_in[4];  // [2H]
    const float* W2    = (const float*)d_in[5];  // [2H,1]
    const float* b2    = (const float*)d_in[6];  // [1]
    float* out = (float*)d_out;

    fused_all<<<dim3(S, B), 192>>>(v_emb, W1, b1, gamma, beta, W2, b2, out);
}

// round 10
// speedup vs baseline: 1.1101x; 1.1101x over previous
#include <cuda_runtime.h>
#include <math.h>

// Problem dims (fixed by reference)
#define B   128
#define N   2048
#define H   768
#define H2  1536
#define S   8           // N-splits for pooling (1024 blocks = one resident wave)
#define NPS (N / S)     // 256 rows per split
#define KS  3           // k-splits for gemm
#define KPS (H / KS)    // 256 k per split
#define NBLK (S * B)    // 1024 pool blocks (all resident: 148*7=1036)
#define GBLK 144        // gemm_ln blocks (< 148 SMs -> all resident)
#define LN_EPS 1e-5f

// Scratch (static device globals; no allocation allowed)
__device__ float g_partial[B * S * H];     // 3.1 MB
__device__ float g_pooled[B * H];          // 393 KB
__device__ float g_hp[KS * B * H2];        // 2.4 MB gemm k-split partials

// grid-barrier state (epoch-based; persists across graph replays)
__device__ unsigned g_cnt1 = 0u, g_gen1 = 0u;   // pool kernel
__device__ unsigned g_cnt2 = 0u, g_gen2 = 0u;   // gemm_ln kernel

// ---------------------------------------------------------------------------
// Kernel 1: fused mean-pool (partial + fold). grid = (S=8, B) = 1024 blocks,
// 192 threads, __launch_bounds__(192,7) -> all resident (proven R8: 118.9us,
// 85% of HBM spec).
// ---------------------------------------------------------------------------
__global__ void __launch_bounds__(192, 7) pool_fused(const float* __restrict__ v) {
    const int s = blockIdx.x;
    const int b = blockIdx.y;
    const int t = threadIdx.x;              // 0..191, 192*4 = 768 = H

    unsigned base_gen = 0;
    if (t == 0) base_gen = *(volatile unsigned*)&g_gen1;

    const float4* p = reinterpret_cast<const float4*>(
        v + ((size_t)b * N + (size_t)s * NPS) * H) + t;
    const int stride = H / 4;

    float4 a0 = make_float4(0.f,0.f,0.f,0.f), a1 = a0, a2 = a0, a3 = a0;
    #pragma unroll 1
    for (int n = 0; n < NPS; n += 4) {
        float4 x0 = __ldcs(p + (n + 0) * stride);
        float4 x1 = __ldcs(p + (n + 1) * stride);
        float4 x2 = __ldcs(p + (n + 2) * stride);
        float4 x3 = __ldcs(p + (n + 3) * stride);
        a0.x += x0.x; a0.y += x0.y; a0.z += x0.z; a0.w += x0.w;
        a1.x += x1.x; a1.y += x1.y; a1.z += x1.z; a1.w += x1.w;
        a2.x += x2.x; a2.y += x2.y; a2.z += x2.z; a2.w += x2.w;
        a3.x += x3.x; a3.y += x3.y; a3.z += x3.z; a3.w += x3.w;
    }
    float4 acc;
    acc.x = (a0.x + a1.x) + (a2.x + a3.x);
    acc.y = (a0.y + a1.y) + (a2.y + a3.y);
    acc.z = (a0.z + a1.z) + (a2.z + a3.z);
    acc.w = (a0.w + a1.w) + (a2.w + a3.w);
    *(reinterpret_cast<float4*>(g_partial + ((size_t)b * S + s) * H) + t) = acc;

    // grid barrier (all 1024 blocks resident by construction)
    __syncthreads();
    if (t == 0) {
        const unsigned target = base_gen + 1u;
        __threadfence();
        if (atomicAdd(&g_cnt1, 1u) == (unsigned)(NBLK - 1)) {
            g_cnt1 = 0u;
            __threadfence();
            *(volatile unsigned*)&g_gen1 = target;
        } else if (s == 0) {
            while ((int)(*(volatile unsigned*)&g_gen1 - target) < 0)
                __nanosleep(64);
        }
        __threadfence();
    }
    __syncthreads();

    // fold S partials, scale by 1/N (128 blocks participate)
    if (s == 0) {
        float4 r = make_float4(0.f, 0.f, 0.f, 0.f);
        #pragma unroll
        for (int ss = 0; ss < S; ss++) {
            float4 x = *(reinterpret_cast<const float4*>(
                g_partial + ((size_t)b * S + ss) * H) + t);
            r.x += x.x; r.y += x.y; r.z += x.z; r.w += x.w;
        }
        const float inv = 1.0f / (float)N;
        r.x *= inv; r.y *= inv; r.z *= inv; r.w *= inv;
        *(reinterpret_cast<float4*>(g_pooled + (size_t)b * H) + t) = r;
    }
}

// ---------------------------------------------------------------------------
// Kernel 2: fused GEMM + LayerNorm/head.  grid = (24,2,3) = 144 blocks
// (< 148 SMs -> all resident -> grid barrier safe), 256 threads.
// Phase A: k-split GEMM partials (R8-optimal 64b x 64f x 32k tiles).
// Barrier. Phase B: 128 blocks do fold+bias+GELU+LN+head+one-hot.
// ---------------------------------------------------------------------------
#define GF 64
#define GB 64
#define GK 32
#define SPLD 68

__global__ void __launch_bounds__(256) gemm_ln(
    const float* __restrict__ W1, const float* __restrict__ b1,
    const float* __restrict__ gamma, const float* __restrict__ beta,
    const float* __restrict__ W2, const float* __restrict__ b2,
    float* __restrict__ out)
{
    __shared__ __align__(16) float sp[GK][SPLD];   // pooled^T tile [k][b]
    __shared__ __align__(16) float sw[GK][GF];     // W1 tile       [k][f]
    __shared__ float redA[8], redB[8];

    const int t = threadIdx.x;
    const int flat = blockIdx.x + 24 * (blockIdx.y + 2 * blockIdx.z); // 0..143

    unsigned base_gen = 0;
    if (t == 0) base_gen = *(volatile unsigned*)&g_gen2;

    // ======== Phase A: GEMM partials ========
    {
        const int fbase = blockIdx.x * GF;
        const int bbase = blockIdx.y * GB;
        const int k0    = blockIdx.z * KPS;
        const int tx = t & 15;
        const int ty = t >> 4;

        float acc[4][4];
        #pragma unroll
        for (int i = 0; i < 4; i++)
            #pragma unroll
            for (int j = 0; j < 4; j++) acc[i][j] = 0.f;

        for (int kt = 0; kt < KPS; kt += GK) {
            #pragma unroll
            for (int i = t; i < GB * GK; i += 256) {
                int bb = i >> 5, kk = i & 31;
                sp[kk][bb] = g_pooled[(bbase + bb) * H + k0 + kt + kk];
            }
            #pragma unroll
            for (int i = t; i < GK * GF; i += 256) {
                int kk = i >> 6, ff = i & 63;
                sw[kk][ff] = W1[(size_t)(k0 + kt + kk) * H2 + fbase + ff];
            }
            __syncthreads();

            #pragma unroll
            for (int kk = 0; kk < GK; kk++) {
                float4 wv = *reinterpret_cast<const float4*>(&sw[kk][tx * 4]);
                float4 pv = *reinterpret_cast<const float4*>(&sp[kk][ty * 4]);
                const float pb[4] = {pv.x, pv.y, pv.z, pv.w};
                const float wf[4] = {wv.x, wv.y, wv.z, wv.w};
                #pragma unroll
                for (int bi = 0; bi < 4; bi++)
                    #pragma unroll
                    for (int fi = 0; fi < 4; fi++)
                        acc[bi][fi] += pb[bi] * wf[fi];
            }
            __syncthreads();
        }

        float* dst = g_hp + (size_t)blockIdx.z * (B * H2);
        #pragma unroll
        for (int bi = 0; bi < 4; bi++) {
            int row = bbase + ty * 4 + bi;
            float4 o = make_float4(acc[bi][0], acc[bi][1], acc[bi][2], acc[bi][3]);
            *reinterpret_cast<float4*>(dst + (size_t)row * H2 + fbase + tx * 4) = o;
        }
    }

    // ======== grid barrier over 144 blocks ========
    __threadfence();
    __syncthreads();
    if (t == 0) {
        const unsigned target = base_gen + 1u;
        if (atomicAdd(&g_cnt2, 1u) == (unsigned)(GBLK - 1)) {
            g_cnt2 = 0u;
            __threadfence();
            *(volatile unsigned*)&g_gen2 = target;
        } else if (flat < B) {
            while ((int)(*(volatile unsigned*)&g_gen2 - target) < 0)
                __nanosleep(64);
        }
        __threadfence();
    }
    __syncthreads();

    if (flat >= B) return;

    // ======== Phase B: fold KS partials + bias + GELU + LN + head ========
    {
        const int b = flat;
        const int w = t >> 5, l = t & 31;   // 8 warps
        const size_t rowoff = (size_t)b * H2;
        const float r2 = 0.70710678118654752f;

        // 384 float4 positions over 256 threads: pos0 = t, pos1 = 256+t (t<128)
        float4 xv0, xv1;
        float s = 0.f, sq = 0.f;
        {
            float4 bb = *reinterpret_cast<const float4*>(b1 + t * 4);
            float4 pa = *reinterpret_cast<const float4*>(g_hp + rowoff + t * 4);
            float4 pc = *reinterpret_cast<const float4*>(g_hp + (size_t)B * H2 + rowoff + t * 4);
            float4 pd = *reinterpret_cast<const float4*>(g_hp + 2 * (size_t)B * H2 + rowoff + t * 4);
            float h0 = pa.x + pc.x + pd.x + bb.x;
            float h1 = pa.y + pc.y + pd.y + bb.y;
            float h2 = pa.z + pc.z + pd.z + bb.z;
            float h3 = pa.w + pc.w + pd.w + bb.w;
            xv0.x = 0.5f * h0 * (1.0f + erff(h0 * r2));
            xv0.y = 0.5f * h1 * (1.0f + erff(h1 * r2));
            xv0.z = 0.5f * h2 * (1.0f + erff(h2 * r2));
            xv0.w = 0.5f * h3 * (1.0f + erff(h3 * r2));
            s  += (xv0.x + xv0.y) + (xv0.z + xv0.w);
            sq += (xv0.x * xv0.x + xv0.y * xv0.y) + (xv0.z * xv0.z + xv0.w * xv0.w);
        }
        if (t < 128) {
            const int pos = 256 + t;
            float4 bb = *reinterpret_cast<const float4*>(b1 + pos * 4);
            float4 pa = *reinterpret_cast<const float4*>(g_hp + rowoff + pos * 4);
            float4 pc = *reinterpret_cast<const float4*>(g_hp + (size_t)B * H2 + rowoff + pos * 4);
            float4 pd = *reinterpret_cast<const float4*>(g_hp + 2 * (size_t)B * H2 + rowoff + pos * 4);
            float h0 = pa.x + pc.x + pd.x + bb.x;
            float h1 = pa.y + pc.y + pd.y + bb.y;
            float h2 = pa.z + pc.z + pd.z + bb.z;
            float h3 = pa.w + pc.w + pd.w + bb.w;
            xv1.x = 0.5f * h0 * (1.0f + erff(h0 * r2));
            xv1.y = 0.5f * h1 * (1.0f + erff(h1 * r2));
            xv1.z = 0.5f * h2 * (1.0f + erff(h2 * r2));
            xv1.w = 0.5f * h3 * (1.0f + erff(h3 * r2));
            s  += (xv1.x + xv1.y) + (xv1.z + xv1.w);
            sq += (xv1.x * xv1.x + xv1.y * xv1.y) + (xv1.z * xv1.z + xv1.w * xv1.w);
        }

        #pragma unroll
        for (int o = 16; o; o >>= 1) {
            s  += __shfl_xor_sync(0xFFFFFFFFu, s,  o);
            sq += __shfl_xor_sync(0xFFFFFFFFu, sq, o);
        }
        if (l == 0) { redA[w] = s; redB[w] = sq; }
        __syncthreads();
        if (t < 32) {
            float a  = (l < 8) ? redA[l] : 0.f;
            float bq = (l < 8) ? redB[l] : 0.f;
            #pragma unroll
            for (int o = 4; o; o >>= 1) {
                a  += __shfl_xor_sync(0xFFFFFFFFu, a,  o);
                bq += __shfl_xor_sync(0xFFFFFFFFu, bq, o);
            }
            if (l == 0) { redA[0] = a; redB[0] = bq; }
        }
        __syncthreads();

        const float mu   = redA[0] * (1.0f / (float)H2);
        const float var  = redB[0] * (1.0f / (float)H2) - mu * mu;
        const float rstd = rsqrtf(var + LN_EPS);
        __syncthreads();   // protect redA/redB reuse

        float local = 0.f;
        {
            float4 gm = *reinterpret_cast<const float4*>(gamma + t * 4);
            float4 bt = *reinterpret_cast<const float4*>(beta  + t * 4);
            float4 w2 = *reinterpret_cast<const float4*>(W2    + t * 4);
            float y0 = (xv0.x - mu) * rstd * gm.x + bt.x;
            float y1 = (xv0.y - mu) * rstd * gm.y + bt.y;
            float y2 = (xv0.z - mu) * rstd * gm.z + bt.z;
            float y3 = (xv0.w - mu) * rstd * gm.w + bt.w;
            local += (y0 * w2.x + y1 * w2.y) + (y2 * w2.z + y3 * w2.w);
        }
        if (t < 128) {
            const int pos = 256 + t;
            float4 gm = *reinterpret_cast<const float4*>(gamma + pos * 4);
            float4 bt = *reinterpret_cast<const float4*>(beta  + pos * 4);
            float4 w2 = *reinterpret_cast<const float4*>(W2    + pos * 4);
            float y0 = (xv1.x - mu) * rstd * gm.x + bt.x;
            float y1 = (xv1.y - mu) * rstd * gm.y + bt.y;
            float y2 = (xv1.z - mu) * rstd * gm.z + bt.z;
            float y3 = (xv1.w - mu) * rstd * gm.w + bt.w;
            local += (y0 * w2.x + y1 * w2.y) + (y2 * w2.z + y3 * w2.w);
        }
        #pragma unroll
        for (int o = 16; o; o >>= 1)
            local += __shfl_xor_sync(0xFFFFFFFFu, local, o);
        if (l == 0) redA[w] = local;
        __syncthreads();
        if (t < 32) {
            float a = (l < 8) ? redA[l] : 0.f;
            #pragma unroll
            for (int o = 4; o; o >>= 1)
                a += __shfl_xor_sync(0xFFFFFFFFu, a, o);
            if (l == 0) redA[0] = a;
        }
        __syncthreads();

        const float pred = redA[0] + b2[0];
        if (t == 0) out[b] = pred;

        // one-hot logits: round-half-even matches jnp.round; clamp [0,15]
        if (t < 16) {
            float r = rintf(pred);
            r = fminf(fmaxf(r, 0.f), 15.f);
            int aid = (int)r;
            out[B + b * 16 + t] = (t == aid) ? 1.0f : 0.0f;
        }
    }
}

// ---------------------------------------------------------------------------
extern "C" void kernel_launch(void* const* d_in, const int* in_sizes, int n_in,
                              void* d_out, int out_size) {
    const float* v_emb = (const float*)d_in[0];  // [B,N,H]
    const float* W1    = (const float*)d_in[1];  // [H,2H]
    const float* b1    = (const float*)d_in[2];  // [2H]
    const float* gamma = (const float*)d_in[3];  // [2H]
    const float* beta  = (const float*)d_in[4];  // [2H]
    const float* W2    = (const float*)d_in[5];  // [2H,1]
    const float* b2    = (const float*)d_in[6];  // [1]
    float* out = (float*)d_out;

    pool_fused<<<dim3(S, B), 192>>>(v_emb);
    gemm_ln<<<dim3(H2 / GF, B / GB, KS), 256>>>(W1, b1, gamma, beta, W2, b2, out);
}

// round 12
// speedup vs baseline: 1.1328x; 1.0205x over previous
#include <cuda_runtime.h>
#include <math.h>

// Problem dims (fixed by reference)
#define B   128
#define N   2048
#define H   768
#define H2  1536
#define S   8           // N-splits for pooling (1024 blocks = one resident wave)
#define NPS (N / S)     // 256 rows per split
#define KS  3           // k-splits for gemm
#define KPS (H / KS)    // 256 k per split
#define NBLK (S * B)    // 1024 pool blocks (all resident: 148*7=1036)
#define LN_EPS 1e-5f

// Scratch (static device globals; no allocation allowed)
__device__ float g_partial[B * S * H];     // 3.1 MB
__device__ float g_pooled[B * H];          // 393 KB
__device__ float g_hp[KS * B * H2];        // 2.4 MB gemm k-split partials

// grid-barrier state (epoch-based; persists across graph replays)
__device__ unsigned g_bar_count = 0u;
__device__ unsigned g_bar_gen   = 0u;

// ---- packed f32x2 helpers (FFMA2: PTX-only, 2x fp32 FMA throughput) ----
__device__ __forceinline__ unsigned long long pack2(float lo, float hi) {
    unsigned long long r;
    asm("mov.b64 %0, {%1, %2};" : "=l"(r) : "f"(lo), "f"(hi));
    return r;
}
__device__ __forceinline__ unsigned long long fma2(
    unsigned long long a, unsigned long long b, unsigned long long c) {
    unsigned long long d;
    asm("fma.rn.f32x2 %0, %1, %2, %3;" : "=l"(d) : "l"(a), "l"(b), "l"(c));
    return d;
}
__device__ __forceinline__ void unpack2(unsigned long long v, float& lo, float& hi) {
    asm("mov.b64 {%0, %1}, %2;" : "=f"(lo), "=f"(hi) : "l"(v));
}

// ---------------------------------------------------------------------------
// Kernel 1: fused mean-pool (partial + fold). grid = (S=8, B) = 1024 blocks,
// 192 threads, __launch_bounds__(192,7) -> all resident.
// Proven R8: 118.9us, 85% of HBM spec. DO NOT TOUCH.
// ---------------------------------------------------------------------------
__global__ void __launch_bounds__(192, 7) pool_fused(const float* __restrict__ v) {
    const int s = blockIdx.x;
    const int b = blockIdx.y;
    const int t = threadIdx.x;              // 0..191, 192*4 = 768 = H

    unsigned base_gen = 0;
    if (t == 0) base_gen = *(volatile unsigned*)&g_bar_gen;

    const float4* p = reinterpret_cast<const float4*>(
        v + ((size_t)b * N + (size_t)s * NPS) * H) + t;
    const int stride = H / 4;

    float4 a0 = make_float4(0.f,0.f,0.f,0.f), a1 = a0, a2 = a0, a3 = a0;
    #pragma unroll 1
    for (int n = 0; n < NPS; n += 4) {
        float4 x0 = __ldcs(p + (n + 0) * stride);
        float4 x1 = __ldcs(p + (n + 1) * stride);
        float4 x2 = __ldcs(p + (n + 2) * stride);
        float4 x3 = __ldcs(p + (n + 3) * stride);
        a0.x += x0.x; a0.y += x0.y; a0.z += x0.z; a0.w += x0.w;
        a1.x += x1.x; a1.y += x1.y; a1.z += x1.z; a1.w += x1.w;
        a2.x += x2.x; a2.y += x2.y; a2.z += x2.z; a2.w += x2.w;
        a3.x += x3.x; a3.y += x3.y; a3.z += x3.z; a3.w += x3.w;
    }
    float4 acc;
    acc.x = (a0.x + a1.x) + (a2.x + a3.x);
    acc.y = (a0.y + a1.y) + (a2.y + a3.y);
    acc.z = (a0.z + a1.z) + (a2.z + a3.z);
    acc.w = (a0.w + a1.w) + (a2.w + a3.w);
    *(reinterpret_cast<float4*>(g_partial + ((size_t)b * S + s) * H) + t) = acc;

    // grid barrier (all 1024 blocks resident by construction)
    __syncthreads();
    if (t == 0) {
        const unsigned target = base_gen + 1u;
        __threadfence();
        if (atomicAdd(&g_bar_count, 1u) == (unsigned)(NBLK - 1)) {
            g_bar_count = 0u;
            __threadfence();
            *(volatile unsigned*)&g_bar_gen = target;
        } else if (s == 0) {
            while ((int)(*(volatile unsigned*)&g_bar_gen - target) < 0)
                __nanosleep(64);
        }
        __threadfence();
    }
    __syncthreads();

    // fold S partials, scale by 1/N (128 blocks participate)
    if (s == 0) {
        float4 r = make_float4(0.f, 0.f, 0.f, 0.f);
        #pragma unroll
        for (int ss = 0; ss < S; ss++) {
            float4 x = *(reinterpret_cast<const float4*>(
                g_partial + ((size_t)b * S + ss) * H) + t);
            r.x += x.x; r.y += x.y; r.z += x.z; r.w += x.w;
        }
        const float inv = 1.0f / (float)N;
        r.x *= inv; r.y *= inv; r.z *= inv; r.w *= inv;
        *(reinterpret_cast<float4*>(g_pooled + (size_t)b * H) + t) = r;
    }
}

// ---------------------------------------------------------------------------
// Kernel 2: k-split GEMM partials with packed FFMA2 inner loop.
// grid = (24 f-tiles, 2 b-tiles, 3 k-splits) = 144 blocks, 256 threads.
// Thread tile 4b x 4f as 4b x 2 f-pairs: 8 FFMA2 per k (= 16 FMA).
// ---------------------------------------------------------------------------
#define GF 64   // features per block tile
#define GB 64   // batch per block tile
#define GK 32   // k per smem tile
#define SPLD 68 // padded sp row

__global__ void __launch_bounds__(256) gemm_part(const float* __restrict__ W1) {
    __shared__ __align__(16) float sp[GK][SPLD];    // pooled^T tile: [k][b]
    __shared__ __align__(16) float sw[GK][GF];      // W1 tile:       [k][f]

    const int fbase = blockIdx.x * GF;
    const int bbase = blockIdx.y * GB;
    const int k0    = blockIdx.z * KPS;
    const int t  = threadIdx.x;
    const int tx = t & 15;            // f group
    const int ty = t >> 4;            // b group

    unsigned long long acc2[4][2];    // [bi][f-pair]
    const unsigned long long zero2 = pack2(0.f, 0.f);
    #pragma unroll
    for (int i = 0; i < 4; i++) { acc2[i][0] = zero2; acc2[i][1] = zero2; }

    for (int kt = 0; kt < KPS; kt += GK) {
        #pragma unroll
        for (int i = t; i < GB * GK; i += 256) {
            int bb = i >> 5, kk = i & 31;
            sp[kk][bb] = g_pooled[(bbase + bb) * H + k0 + kt + kk];
        }
        #pragma unroll
        for (int i = t; i < GK * GF; i += 256) {
            int kk = i >> 6, ff = i & 63;
            sw[kk][ff] = W1[(size_t)(k0 + kt + kk) * H2 + fbase + ff];
        }
        __syncthreads();

        #pragma unroll
        for (int kk = 0; kk < GK; kk++) {
            float4 wv = *reinterpret_cast<const float4*>(&sw[kk][tx * 4]);
            float4 pv = *reinterpret_cast<const float4*>(&sp[kk][ty * 4]);
            unsigned long long w0 = pack2(wv.x, wv.y);
            unsigned long long w1 = pack2(wv.z, wv.w);
            unsigned long long p0 = pack2(pv.x, pv.x);
            unsigned long long p1 = pack2(pv.y, pv.y);
            unsigned long long p2 = pack2(pv.z, pv.z);
            unsigned long long p3 = pack2(pv.w, pv.w);
            acc2[0][0] = fma2(p0, w0, acc2[0][0]);
            acc2[0][1] = fma2(p0, w1, acc2[0][1]);
            acc2[1][0] = fma2(p1, w0, acc2[1][0]);
            acc2[1][1] = fma2(p1, w1, acc2[1][1]);
            acc2[2][0] = fma2(p2, w0, acc2[2][0]);
            acc2[2][1] = fma2(p2, w1, acc2[2][1]);
            acc2[3][0] = fma2(p3, w0, acc2[3][0]);
            acc2[3][1] = fma2(p3, w1, acc2[3][1]);
        }
        __syncthreads();
    }

    float* dst = g_hp + (size_t)blockIdx.z * (B * H2);
    #pragma unroll
    for (int bi = 0; bi < 4; bi++) {
        int row = bbase + ty * 4 + bi;
        float4 o;
        unpack2(acc2[bi][0], o.x, o.y);
        unpack2(acc2[bi][1], o.z, o.w);
        *reinterpret_cast<float4*>(dst + (size_t)row * H2 + fbase + tx * 4) = o;
    }
}

// ---------------------------------------------------------------------------
// Kernel 3: fused (k-partial fold + bias + exact GELU) -> LayerNorm -> head
// -> one-hot logits.  grid = B, block = 384 (one float4 of H2 per thread).
// Output layout: d_out[0..B) = pred; d_out[B..B+B*16) = logits.
// ---------------------------------------------------------------------------
__global__ void __launch_bounds__(384) ln_head(const float* __restrict__ b1,
                                               const float* __restrict__ gamma,
                                               const float* __restrict__ beta,
                                               const float* __restrict__ W2,
                                               const float* __restrict__ b2,
                                               float* __restrict__ out) {
    const int b = blockIdx.x;
    const int t = threadIdx.x;          // 0..383
    const int w = t >> 5, l = t & 31;   // 12 warps

    const size_t off = (size_t)b * H2 + t * 4;
    float4 pa = *reinterpret_cast<const float4*>(g_hp + off);
    float4 pc = *reinterpret_cast<const float4*>(g_hp + (size_t)B * H2 + off);
    float4 pd = *reinterpret_cast<const float4*>(g_hp + 2 * (size_t)B * H2 + off);
    float4 bb = *reinterpret_cast<const float4*>(b1 + t * 4);

    // fold k-splits + bias, exact GELU (matches approximate=False)
    const float r2 = 0.70710678118654752f;
    float h0 = pa.x + pc.x + pd.x + bb.x;
    float h1 = pa.y + pc.y + pd.y + bb.y;
    float h2 = pa.z + pc.z + pd.z + bb.z;
    float h3 = pa.w + pc.w + pd.w + bb.w;
    float4 x;
    x.x = 0.5f * h0 * (1.0f + erff(h0 * r2));
    x.y = 0.5f * h1 * (1.0f + erff(h1 * r2));
    x.z = 0.5f * h2 * (1.0f + erff(h2 * r2));
    x.w = 0.5f * h3 * (1.0f + erff(h3 * r2));

    float s  = (x.x + x.y) + (x.z + x.w);
    float sq = (x.x * x.x + x.y * x.y) + (x.z * x.z + x.w * x.w);

    __shared__ float sA[12], sB[12];
    #pragma unroll
    for (int o = 16; o; o >>= 1) {
        s  += __shfl_xor_sync(0xFFFFFFFFu, s,  o);
        sq += __shfl_xor_sync(0xFFFFFFFFu, sq, o);
    }
    if (l == 0) { sA[w] = s; sB[w] = sq; }
    __syncthreads();
    if (t < 32) {
        float a  = (l < 12) ? sA[l] : 0.f;
        float bq = (l < 12) ? sB[l] : 0.f;
        #pragma unroll
        for (int o = 8; o; o >>= 1) {
            a  += __shfl_xor_sync(0xFFFFFFFFu, a,  o);
            bq += __shfl_xor_sync(0xFFFFFFFFu, bq, o);
        }
        if (l == 0) { sA[0] = a; sB[0] = bq; }
    }
    __syncthreads();

    const float mu  = sA[0] * (1.0f / (float)H2);
    const float var = sB[0] * (1.0f / (float)H2) - mu * mu;
    const float rstd = rsqrtf(var + LN_EPS);

    __syncthreads();   // protect sA/sB reuse below

    float4 gm = *reinterpret_cast<const float4*>(gamma + t * 4);
    float4 bt = *reinterpret_cast<const float4*>(beta  + t * 4);
    float4 w2 = *reinterpret_cast<const float4*>(W2    + t * 4);

    float y0 = (x.x - mu) * rstd * gm.x + bt.x;
    float y1 = (x.y - mu) * rstd * gm.y + bt.y;
    float y2 = (x.z - mu) * rstd * gm.z + bt.z;
    float y3 = (x.w - mu) * rstd * gm.w + bt.w;

    float local = (y0 * w2.x + y1 * w2.y) + (y2 * w2.z + y3 * w2.w);
    #pragma unroll
    for (int o = 16; o; o >>= 1)
        local += __shfl_xor_sync(0xFFFFFFFFu, local, o);
    if (l == 0) sA[w] = local;
    __syncthreads();
    if (t < 32) {
        float a = (l < 12) ? sA[l] : 0.f;
        #pragma unroll
        for (int o = 8; o; o >>= 1)
            a += __shfl_xor_sync(0xFFFFFFFFu, a, o);
        if (l == 0) sA[0] = a;
    }
    __syncthreads();

    const float pred = sA[0] + b2[0];

    if (t == 0) out[b] = pred;

    // one-hot logits: round-half-even matches jnp.round; clamp [0,15]
    if (t < 16) {
        float r = rintf(pred);
        r = fminf(fmaxf(r, 0.f), 15.f);
        int aid = (int)r;
        out[B + b * 16 + t] = (t == aid) ? 1.0f : 0.0f;
    }
}

// ---------------------------------------------------------------------------
extern "C" void kernel_launch(void* const* d_in, const int* in_sizes, int n_in,
                              void* d_out, int out_size) {
    const float* v_emb = (const float*)d_in[0];  // [B,N,H]
    const float* W1    = (const float*)d_in[1];  // [H,2H]
    const float* b1    = (const float*)d_in[2];  // [2H]
    const float* gamma = (const float*)d_in[3];  // [2H]
    const float* beta  = (const float*)d_in[4];  // [2H]
    const float* W2    = (const float*)d_in[5];  // [2H,1]
    const float* b2    = (const float*)d_in[6];  // [1]
    float* out = (float*)d_out;

    pool_fused<<<dim3(S, B), 192>>>(v_emb);
    gemm_part<<<dim3(H2 / GF, B / GB, KS), 256>>>(W1);
    ln_head<<<B, 384>>>(b1, gamma, beta, W2, b2, out);
}